// round 2
// baseline (speedup 1.0000x reference)
#include <cuda_runtime.h>
#include <math.h>

#define B_  64
#define C_  1000
#define F_  2048
#define KS  8
#define CP  1024   // padded C stride

// ---------------- scratch (static __device__, no allocations) ----------------
__device__ float g_p_dot[KS][B_ * CP];    // partials: x @ centroids^T
__device__ float g_p_hall[KS][B_ * CP];   // partials: x @ W_hall^T
__device__ float g_p_sel[KS][B_ * F_];    // partials: x @ W_sel^T
__device__ float g_p_mem[KS][B_ * F_];    // partials: vm @ centroids
__device__ float g_p_cos[KS][B_ * CP];    // partials: feat @ W_cos^T
__device__ float g_hall[B_ * CP];
__device__ float g_vm[B_ * CP];
__device__ float g_feat[B_ * F_];
__device__ float g_cn2[CP];
__device__ float g_wn[CP];
__device__ float g_xn2[B_];
__device__ float g_reach[B_];
__device__ float g_scale[B_];

// ---------------- row-wise squared norms / norms (float4 + warp shuffle) ----------------
__global__ __launch_bounds__(256) void norms_kernel(const float* __restrict__ centroids,
                                                    const float* __restrict__ W_cos,
                                                    const float* __restrict__ x) {
    int bid = blockIdx.x;
    const float* src;
    int mode, idx;
    if (bid < C_)            { src = centroids + (size_t)bid * F_;        mode = 0; idx = bid; }
    else if (bid < 2 * C_)   { src = W_cos + (size_t)(bid - C_) * F_;     mode = 1; idx = bid - C_; }
    else                     { src = x + (size_t)(bid - 2 * C_) * F_;     mode = 2; idx = bid - 2 * C_; }
    const float4* s4 = (const float4*)src;
    float s = 0.f;
    for (int i = threadIdx.x; i < F_ / 4; i += 256) {
        float4 v = s4[i];
        s += v.x * v.x + v.y * v.y + v.z * v.z + v.w * v.w;
    }
#pragma unroll
    for (int o = 16; o > 0; o >>= 1) s += __shfl_xor_sync(0xffffffffu, s, o);
    __shared__ float red[8];
    if ((threadIdx.x & 31) == 0) red[threadIdx.x >> 5] = s;
    __syncthreads();
    if (threadIdx.x == 0) {
        float tot = 0.f;
#pragma unroll
        for (int w = 0; w < 8; w++) tot += red[w];
        if (mode == 0)      g_cn2[idx] = tot;
        else if (mode == 1) g_wn[idx]  = sqrtf(tot);
        else                g_xn2[idx] = tot;
    }
}

// ---------------- shared NT GEMM core: 64x64 tile, BK=16, 128 threads, 4x8 micro ----------------
// P[m, n0+n] = sum_{k in [k0,kend)} A[m,k] * Bm[n0+n, k].  (kend-k0) % 16 == 0 required.
__device__ __forceinline__ void gemm64_core_nt(const float* __restrict__ A, int lda,
                                               const float* __restrict__ Bm, int ldb,
                                               float* __restrict__ P, int ldp,
                                               int N, int n0, int k0, int kend) {
    __shared__ float As[16][68];
    __shared__ float Bs[16][68];
    const int tid = threadIdx.x;
    const int tx  = tid & 7;        // n micro: 8 wide
    const int ty  = tid >> 3;       // m micro: 4 tall (16 groups)
    const int lr  = tid >> 2;       // loader row 0..31
    const int lkq = (tid & 3) * 4;  // loader k-quad

    float acc[4][8];
#pragma unroll
    for (int i = 0; i < 4; i++)
#pragma unroll
        for (int j = 0; j < 8; j++) acc[i][j] = 0.f;

    const int br0 = n0 + lr, br1 = n0 + lr + 32;

    for (int kb = k0; kb < kend; kb += 16) {
        // A tile: 64 rows (M fixed = 64), transpose-store As[k][m]
        float4 a0 = *(const float4*)&A[(size_t)lr * lda + kb + lkq];
        float4 a1 = *(const float4*)&A[(size_t)(lr + 32) * lda + kb + lkq];
        As[lkq + 0][lr] = a0.x; As[lkq + 1][lr] = a0.y;
        As[lkq + 2][lr] = a0.z; As[lkq + 3][lr] = a0.w;
        As[lkq + 0][lr + 32] = a1.x; As[lkq + 1][lr + 32] = a1.y;
        As[lkq + 2][lr + 32] = a1.z; As[lkq + 3][lr + 32] = a1.w;
        // B tile: rows br0, br1 (guard against N), transpose-store Bs[k][n]
        float4 b0 = make_float4(0.f, 0.f, 0.f, 0.f);
        float4 b1 = make_float4(0.f, 0.f, 0.f, 0.f);
        if (br0 < N) b0 = *(const float4*)&Bm[(size_t)br0 * ldb + kb + lkq];
        if (br1 < N) b1 = *(const float4*)&Bm[(size_t)br1 * ldb + kb + lkq];
        Bs[lkq + 0][lr] = b0.x; Bs[lkq + 1][lr] = b0.y;
        Bs[lkq + 2][lr] = b0.z; Bs[lkq + 3][lr] = b0.w;
        Bs[lkq + 0][lr + 32] = b1.x; Bs[lkq + 1][lr + 32] = b1.y;
        Bs[lkq + 2][lr + 32] = b1.z; Bs[lkq + 3][lr + 32] = b1.w;
        __syncthreads();
#pragma unroll
        for (int kk = 0; kk < 16; kk++) {
            float4 av = *(const float4*)&As[kk][ty * 4];
            float4 bv0 = *(const float4*)&Bs[kk][tx * 8];
            float4 bv1 = *(const float4*)&Bs[kk][tx * 8 + 4];
            const float ar[4] = {av.x, av.y, av.z, av.w};
            const float br[8] = {bv0.x, bv0.y, bv0.z, bv0.w, bv1.x, bv1.y, bv1.z, bv1.w};
#pragma unroll
            for (int i = 0; i < 4; i++)
#pragma unroll
                for (int j = 0; j < 8; j++) acc[i][j] += ar[i] * br[j];
        }
        __syncthreads();
    }
    // epilogue: N % 8 == 0 for all our cases, so 8-chunks never straddle N
    const int n = n0 + tx * 8;
    if (n < N) {
#pragma unroll
        for (int i = 0; i < 4; i++) {
            int m = ty * 4 + i;
            *(float4*)&P[(size_t)m * ldp + n]     = make_float4(acc[i][0], acc[i][1], acc[i][2], acc[i][3]);
            *(float4*)&P[(size_t)m * ldp + n + 4] = make_float4(acc[i][4], acc[i][5], acc[i][6], acc[i][7]);
        }
    }
}

// ---------------- fused x-side GEMM: x @ [centroids; W_hall; W_sel]^T ----------------
__global__ __launch_bounds__(128) void mega_xgemm(const float* __restrict__ x,
                                                  const float* __restrict__ centroids,
                                                  const float* __restrict__ W_hall,
                                                  const float* __restrict__ W_sel) {
    const int t  = blockIdx.x;
    const int ks = blockIdx.y;
    const float* Bm; float* P; int N, n0, ldp;
    if (t < 16)      { Bm = centroids; P = g_p_dot[ks];  N = C_; n0 = t * 64;        ldp = CP; }
    else if (t < 32) { Bm = W_hall;    P = g_p_hall[ks]; N = C_; n0 = (t - 16) * 64; ldp = CP; }
    else             { Bm = W_sel;     P = g_p_sel[ks];  N = F_; n0 = (t - 32) * 64; ldp = F_; }
    gemm64_core_nt(x, F_, Bm, F_, P, ldp, N, n0, ks * 256, ks * 256 + 256);
}

// ---------------- cos GEMM: feat @ W_cos^T ----------------
__global__ __launch_bounds__(128) void cos_gemm(const float* __restrict__ W_cos) {
    gemm64_core_nt(g_feat, F_, W_cos, F_, g_p_cos[blockIdx.y], CP, C_,
                   blockIdx.x * 64, blockIdx.y * 256, blockIdx.y * 256 + 256);
}

// ---------------- mem GEMM (NN): vm @ centroids, K = C (ragged k) ----------------
__global__ __launch_bounds__(128) void mem_gemm(const float* __restrict__ centroids) {
    __shared__ float As[16][68];
    __shared__ float Bs[16][68];
    const int n0   = blockIdx.x * 64;
    const int ks   = blockIdx.y;
    const int k0   = ks * 128;
    const int kend = min(C_, k0 + 128);
    const int tid  = threadIdx.x;
    const int tx   = tid & 7, ty = tid >> 3;
    const int lr   = tid >> 2, lkq = (tid & 3) * 4;
    const int bk   = tid >> 3;           // B loader: k row 0..15
    const int bnq  = (tid & 7) * 8;      // B loader: 8 n's

    float acc[4][8];
#pragma unroll
    for (int i = 0; i < 4; i++)
#pragma unroll
        for (int j = 0; j < 8; j++) acc[i][j] = 0.f;

    for (int kb = k0; kb < kend; kb += 16) {
        if (kb + 16 <= kend) {
            float4 a0 = *(const float4*)&g_vm[lr * CP + kb + lkq];
            float4 a1 = *(const float4*)&g_vm[(lr + 32) * CP + kb + lkq];
            As[lkq + 0][lr] = a0.x; As[lkq + 1][lr] = a0.y;
            As[lkq + 2][lr] = a0.z; As[lkq + 3][lr] = a0.w;
            As[lkq + 0][lr + 32] = a1.x; As[lkq + 1][lr + 32] = a1.y;
            As[lkq + 2][lr + 32] = a1.z; As[lkq + 3][lr + 32] = a1.w;
            int k = kb + bk;
            float4 b0 = *(const float4*)&centroids[(size_t)k * F_ + n0 + bnq];
            float4 b1 = *(const float4*)&centroids[(size_t)k * F_ + n0 + bnq + 4];
            *(float4*)&Bs[bk][bnq]     = b0;
            *(float4*)&Bs[bk][bnq + 4] = b1;
        } else {
#pragma unroll
            for (int i = 0; i < 4; i++) {
                int k = kb + lkq + i;
                As[lkq + i][lr]      = (k < kend) ? g_vm[lr * CP + k] : 0.f;
                As[lkq + i][lr + 32] = (k < kend) ? g_vm[(lr + 32) * CP + k] : 0.f;
            }
            int k = kb + bk;
            float4 b0 = make_float4(0.f, 0.f, 0.f, 0.f);
            float4 b1 = b0;
            if (k < kend) {
                b0 = *(const float4*)&centroids[(size_t)k * F_ + n0 + bnq];
                b1 = *(const float4*)&centroids[(size_t)k * F_ + n0 + bnq + 4];
            }
            *(float4*)&Bs[bk][bnq]     = b0;
            *(float4*)&Bs[bk][bnq + 4] = b1;
        }
        __syncthreads();
#pragma unroll
        for (int kk = 0; kk < 16; kk++) {
            float4 av = *(const float4*)&As[kk][ty * 4];
            float4 bv0 = *(const float4*)&Bs[kk][tx * 8];
            float4 bv1 = *(const float4*)&Bs[kk][tx * 8 + 4];
            const float ar[4] = {av.x, av.y, av.z, av.w};
            const float br[8] = {bv0.x, bv0.y, bv0.z, bv0.w, bv1.x, bv1.y, bv1.z, bv1.w};
#pragma unroll
            for (int i = 0; i < 4; i++)
#pragma unroll
                for (int j = 0; j < 8; j++) acc[i][j] += ar[i] * br[j];
        }
        __syncthreads();
    }
    float* P = g_p_mem[ks];
    const int n = n0 + tx * 8;
#pragma unroll
    for (int i = 0; i < 4; i++) {
        int m = ty * 4 + i;
        *(float4*)&P[(size_t)m * F_ + n]     = make_float4(acc[i][0], acc[i][1], acc[i][2], acc[i][3]);
        *(float4*)&P[(size_t)m * F_ + n + 4] = make_float4(acc[i][4], acc[i][5], acc[i][6], acc[i][7]);
    }
}

// ---------------- per-row: reduce partials, min-dist, softmax, reachability ----------------
__global__ __launch_bounds__(256) void row_softmax_kernel(const float* __restrict__ b_hall) {
    const int b = blockIdx.x;
    const int tid = threadIdx.x;
    __shared__ float r0[256], r1[256];
    float mind2 = 1e30f, maxh = -1e30f;
    const float xn2 = g_xn2[b];
    for (int c = tid; c < C_; c += 256) {
        float dot = 0.f, hv = 0.f;
#pragma unroll
        for (int s = 0; s < KS; s++) {
            dot += g_p_dot[s][b * CP + c];
            hv  += g_p_hall[s][b * CP + c];
        }
        hv += b_hall[c];
        g_hall[b * CP + c] = hv;
        float d2 = xn2 + g_cn2[c] - 2.f * dot;
        mind2 = fminf(mind2, d2);
        maxh  = fmaxf(maxh, hv);
    }
    r0[tid] = mind2; r1[tid] = maxh; __syncthreads();
    for (int o = 128; o > 0; o >>= 1) {
        if (tid < o) { r0[tid] = fminf(r0[tid], r0[tid + o]); r1[tid] = fmaxf(r1[tid], r1[tid + o]); }
        __syncthreads();
    }
    const float md2 = r0[0];
    const float mh  = r1[0];
    __syncthreads();
    float se = 0.f;
    for (int c = tid; c < C_; c += 256) se += __expf(g_hall[b * CP + c] - mh);
    r0[tid] = se; __syncthreads();
    for (int o = 128; o > 0; o >>= 1) {
        if (tid < o) r0[tid] += r0[tid + o];
        __syncthreads();
    }
    const float inv = 1.f / r0[0];
    for (int c = tid; c < C_; c += 256)
        g_vm[b * CP + c] = __expf(g_hall[b * CP + c] - mh) * inv;
    if (tid == 0) g_reach[b] = 10.f / sqrtf(fmaxf(md2, 1e-30f));
}

// ---------------- per-row: feat = reach*(x + tanh(sel)*mem), row norm, outputs ----------------
__global__ __launch_bounds__(256) void combine_kernel(const float* __restrict__ x,
                                                      const float* __restrict__ b_sel,
                                                      float* __restrict__ out, int writeFeat) {
    const int b = blockIdx.x;
    const int tid = threadIdx.x;
    __shared__ float red[256];
    const float reach = g_reach[b];
    float n2 = 0.f;
    for (int f = tid; f < F_; f += 256) {
        float mem = 0.f, sz = 0.f;
#pragma unroll
        for (int s = 0; s < KS; s++) {
            mem += g_p_mem[s][b * F_ + f];
            sz  += g_p_sel[s][b * F_ + f];
        }
        float sel  = tanhf(sz + b_sel[f]);
        float xv   = x[(size_t)b * F_ + f];
        float inf  = sel * mem;
        float feat = reach * (xv + inf);
        g_feat[b * F_ + f] = feat;
        n2 += feat * feat;
        if (writeFeat) {
            out[64000 + b * F_ + f]  = xv;   // direct_feature
            out[195072 + b * F_ + f] = inf;  // infused_feature
        }
    }
    red[tid] = n2; __syncthreads();
    for (int o = 128; o > 0; o >>= 1) {
        if (tid < o) red[tid] += red[tid + o];
        __syncthreads();
    }
    if (tid == 0) g_scale[b] = 16.f / (1.f + sqrtf(red[0]));
}

// ---------------- final logits ----------------
__global__ __launch_bounds__(256) void logits_kernel(float* __restrict__ out) {
    int i = blockIdx.x * 256 + threadIdx.x;
    if (i >= B_ * C_) return;
    int b = i / C_, c = i % C_;
    float s = 0.f;
#pragma unroll
    for (int ss = 0; ss < KS; ss++) s += g_p_cos[ss][b * CP + c];
    out[i] = s * g_scale[b] / g_wn[c];
}

// ---------------- launch ----------------
extern "C" void kernel_launch(void* const* d_in, const int* in_sizes, int n_in,
                              void* d_out, int out_size) {
    const float* x         = (const float*)d_in[0];
    const float* centroids = (const float*)d_in[1];
    const float* W_hall    = (const float*)d_in[2];
    const float* b_hall    = (const float*)d_in[3];
    const float* W_sel     = (const float*)d_in[4];
    const float* b_sel     = (const float*)d_in[5];
    const float* W_cos     = (const float*)d_in[6];
    float* out = (float*)d_out;

    // 1. row norms (centroids, W_cos, x)
    norms_kernel<<<2 * C_ + B_, 256>>>(centroids, W_cos, x);

    // 2. fused x-side GEMMs (dot | hall | sel), split-K
    mega_xgemm<<<dim3(64, KS), 128>>>(x, centroids, W_hall, W_sel);

    // 3. softmax + min-dist + reachability
    row_softmax_kernel<<<B_, 256>>>(b_hall);

    // 4. memory_feature = vm @ centroids
    mem_gemm<<<dim3(32, KS), 128>>>(centroids);

    // 5. feat + direct/infused outputs + row norm
    int writeFeat = (out_size >= 326144) ? 1 : 0;
    combine_kernel<<<B_, 256>>>(x, b_sel, out, writeFeat);

    // 6. cos logits GEMM
    cos_gemm<<<dim3(16, KS), 128>>>(W_cos);

    // 7. final scaled logits
    logits_kernel<<<250, 256>>>(out);
}